// round 1
// baseline (speedup 1.0000x reference)
#include <cuda_runtime.h>
#include <cstdint>

#define N_NODES 50000
#define N_EDGES 800000

// ---------------- static device scratch (no dynamic allocation allowed) ----------------
__device__ float g_q[(size_t)N_NODES * 128];
__device__ float g_k[(size_t)N_NODES * 128];
__device__ float g_v[(size_t)N_NODES * 128];
__device__ float g_hA[(size_t)N_NODES * 128];
__device__ float g_hB[(size_t)N_NODES * 128];
__device__ float g_e[(size_t)N_EDGES * 128];   // per-edge projected edge features (CSR order)
__device__ float g_ea[(size_t)N_EDGES * 32];   // edge_attr permuted to CSR order
__device__ int   g_src[N_EDGES];
__device__ int   g_dst[N_EDGES];
__device__ int   g_esrc[N_EDGES];              // src per CSR slot
__device__ int   g_rowptr[N_NODES + 1];
__device__ int   g_cnt[N_NODES];
__device__ int   g_wofs[N_NODES];
__device__ int   g_flag[1];

// ---------------- edge_index dtype detection (int32 vs int64) ----------------
__global__ void detect_kernel(const void* ei) {
    __shared__ int ok;
    if (threadIdx.x == 0) ok = 1;
    __syncthreads();
    const long long* p = (const long long*)ei;
    long long v = p[threadIdx.x];
    if (!(v >= 0 && v < (long long)N_NODES)) atomicExch(&ok, 0);
    __syncthreads();
    if (threadIdx.x == 0) g_flag[0] = ok;   // 1 => data is int64
}

__global__ void convert_kernel(const void* ei) {
    int i = blockIdx.x * blockDim.x + threadIdx.x;
    int is64 = g_flag[0];
    if (i < N_EDGES) {
        int s, d;
        if (is64) {
            const long long* p = (const long long*)ei;
            s = (int)p[i]; d = (int)p[N_EDGES + i];
        } else {
            const int* p = (const int*)ei;
            s = p[i]; d = p[N_EDGES + i];
        }
        g_src[i] = s; g_dst[i] = d;
    }
    if (i < N_NODES) g_cnt[i] = 0;
}

__global__ void hist_kernel() {
    int i = blockIdx.x * blockDim.x + threadIdx.x;
    if (i < N_EDGES) atomicAdd(&g_cnt[g_dst[i]], 1);
}

// single-block exclusive scan over g_cnt -> g_rowptr, g_wofs
__global__ void scan_kernel() {
    __shared__ int wsum[32];
    __shared__ int carry;
    int tid = threadIdx.x, lane = tid & 31, wid = tid >> 5;
    if (tid == 0) { carry = 0; g_rowptr[0] = 0; }
    __syncthreads();
    for (int base = 0; base < N_NODES; base += 1024) {
        int i = base + tid;
        int v = (i < N_NODES) ? g_cnt[i] : 0;
        int x = v;
        #pragma unroll
        for (int off = 1; off < 32; off <<= 1) {
            int t = __shfl_up_sync(0xffffffffu, x, off);
            if (lane >= off) x += t;
        }
        if (lane == 31) wsum[wid] = x;
        __syncthreads();
        if (wid == 0) {
            int y = wsum[lane];
            #pragma unroll
            for (int off = 1; off < 32; off <<= 1) {
                int t = __shfl_up_sync(0xffffffffu, y, off);
                if (lane >= off) y += t;
            }
            wsum[lane] = y;
        }
        __syncthreads();
        int pre = carry + (wid ? wsum[wid - 1] : 0);
        int incl = pre + x;
        if (i < N_NODES) { g_rowptr[i + 1] = incl; g_wofs[i] = incl - v; }
        __syncthreads();
        if (tid == 0) carry += wsum[31];
        __syncthreads();
    }
}

// one warp per edge: place edge into CSR slot, copy its 32 edge_attr floats
__global__ void scatter_kernel(const float* __restrict__ ea) {
    int w = (blockIdx.x * blockDim.x + threadIdx.x) >> 5;
    int lane = threadIdx.x & 31;
    if (w >= N_EDGES) return;
    int pos = 0;
    if (lane == 0) {
        int d = g_dst[w];
        pos = atomicAdd(&g_wofs[d], 1);
        g_esrc[pos] = g_src[w];
    }
    pos = __shfl_sync(0xffffffffu, pos, 0);
    g_ea[(size_t)pos * 32 + lane] = ea[(size_t)w * 32 + lane];
}

// ---------------- tiled SGEMM: C[M,BN] = A[M,K] @ W[K,BN] + bias ----------------
template <int BN>
__global__ void gemm_kernel(const float* __restrict__ A, const float* __restrict__ W,
                            const float* __restrict__ bias, float* __restrict__ C,
                            int M, int K) {
    constexpr int BM = 64, BK = 32;
    constexpr int CT = BN / 4;     // col threads (each owns 4 cols)
    constexpr int RT = 256 / CT;   // row threads
    constexpr int TM = BM / RT;    // rows per thread
    __shared__ float As[BM][BK + 1];
    __shared__ float Ws[BK][BN];
    int tid = threadIdx.x;
    int ct = tid % CT, rt = tid / CT;
    int row0 = blockIdx.x * BM;
    float acc[TM][4];
    #pragma unroll
    for (int t = 0; t < TM; t++) { acc[t][0] = acc[t][1] = acc[t][2] = acc[t][3] = 0.f; }

    for (int k0 = 0; k0 < K; k0 += BK) {
        // load A tile (64 x 32) as 512 float4s; 2 per thread
        #pragma unroll
        for (int it = 0; it < 2; it++) {
            int f = tid + 256 * it;
            int r = f >> 3, kq = f & 7;
            float4 a = make_float4(0.f, 0.f, 0.f, 0.f);
            int grow = row0 + r;
            if (grow < M) a = *(const float4*)&A[(size_t)grow * K + k0 + kq * 4];
            As[r][kq * 4 + 0] = a.x;
            As[r][kq * 4 + 1] = a.y;
            As[r][kq * 4 + 2] = a.z;
            As[r][kq * 4 + 3] = a.w;
        }
        // load W tile (32 x BN) as 8*BN float4s
        #pragma unroll
        for (int it = 0; it < BN / 32; it++) {
            int f = tid + 256 * it;
            int kk = f / (BN / 4), n4 = f % (BN / 4);
            float4 wv = *(const float4*)&W[(size_t)(k0 + kk) * BN + n4 * 4];
            *(float4*)&Ws[kk][n4 * 4] = wv;
        }
        __syncthreads();
        #pragma unroll
        for (int kk = 0; kk < BK; kk++) {
            float4 wv = *(const float4*)&Ws[kk][ct * 4];
            #pragma unroll
            for (int t = 0; t < TM; t++) {
                float a = As[rt * TM + t][kk];
                acc[t][0] = fmaf(a, wv.x, acc[t][0]);
                acc[t][1] = fmaf(a, wv.y, acc[t][1]);
                acc[t][2] = fmaf(a, wv.z, acc[t][2]);
                acc[t][3] = fmaf(a, wv.w, acc[t][3]);
            }
        }
        __syncthreads();
    }
    float4 bv = make_float4(0.f, 0.f, 0.f, 0.f);
    if (bias) bv = *(const float4*)&bias[ct * 4];
    #pragma unroll
    for (int t = 0; t < TM; t++) {
        int r = row0 + rt * TM + t;
        if (r < M) {
            float4 o = make_float4(acc[t][0] + bv.x, acc[t][1] + bv.y,
                                   acc[t][2] + bv.z, acc[t][3] + bv.w);
            *(float4*)&C[(size_t)r * BN + ct * 4] = o;
        }
    }
}

// ---------------- one warp per dst node: online segment softmax + aggregation ----------------
template <int DOUT>
__global__ void attn_kernel(const float* __restrict__ q, const float* __restrict__ k,
                            const float* __restrict__ v, const float* __restrict__ e,
                            float* __restrict__ h) {
    int w = (blockIdx.x * blockDim.x + threadIdx.x) >> 5;
    if (w >= N_NODES) return;
    int lane = threadIdx.x & 31;
    constexpr int VEC = DOUT / 32;
    float qr[VEC], acc[VEC];
    {
        const float* qp = q + (size_t)w * DOUT + lane * VEC;
        #pragma unroll
        for (int j = 0; j < VEC; j++) { qr[j] = qp[j]; acc[j] = 0.f; }
    }
    float m = -__int_as_float(0x7f800000);  // -inf
    float s = 0.f;
    int beg = g_rowptr[w], end = g_rowptr[w + 1];
    const float scale = rsqrtf((float)DOUT);
    for (int i = beg; i < end; i++) {
        int src = g_esrc[i];
        const float* kp = k + (size_t)src * DOUT + lane * VEC;
        const float* vp = v + (size_t)src * DOUT + lane * VEC;
        const float* ep = e + (size_t)i * DOUT + lane * VEC;
        float ke[VEC], ve[VEC];
        if constexpr (VEC == 4) {
            float4 et = *(const float4*)ep;
            float4 kt = *(const float4*)kp;
            float4 vt = *(const float4*)vp;
            ke[0] = kt.x + et.x; ke[1] = kt.y + et.y; ke[2] = kt.z + et.z; ke[3] = kt.w + et.w;
            ve[0] = vt.x + et.x; ve[1] = vt.y + et.y; ve[2] = vt.z + et.z; ve[3] = vt.w + et.w;
        } else if constexpr (VEC == 2) {
            float2 et = *(const float2*)ep;
            float2 kt = *(const float2*)kp;
            float2 vt = *(const float2*)vp;
            ke[0] = kt.x + et.x; ke[1] = kt.y + et.y;
            ve[0] = vt.x + et.x; ve[1] = vt.y + et.y;
        } else {
            float et = ep[0];
            ke[0] = kp[0] + et;
            ve[0] = vp[0] + et;
        }
        float dot = 0.f;
        #pragma unroll
        for (int j = 0; j < VEC; j++) dot = fmaf(qr[j], ke[j], dot);
        #pragma unroll
        for (int off = 16; off; off >>= 1) dot += __shfl_xor_sync(0xffffffffu, dot, off);
        float alpha = dot * scale;
        float nm = fmaxf(m, alpha);
        float corr = __expf(m - nm);     // 0 when m == -inf
        float wgt = __expf(alpha - nm);
        s = s * corr + wgt;
        #pragma unroll
        for (int j = 0; j < VEC; j++) acc[j] = fmaf(wgt, ve[j], acc[j] * corr);
        m = nm;
    }
    float inv = (s > 0.f) ? 1.f / s : 0.f;
    float* hp = h + (size_t)w * DOUT + lane * VEC;
    #pragma unroll
    for (int j = 0; j < VEC; j++) hp[j] = fmaxf(fmaf(acc[j], inv, hp[j]), 0.f);
}

// ---------------- final linear: out[n] = h3[n,:] @ Wc + bc ----------------
__global__ void final_kernel(const float* __restrict__ h, const float* __restrict__ Wc,
                             const float* __restrict__ bc, float* __restrict__ out) {
    int i = blockIdx.x * blockDim.x + threadIdx.x;
    if (i >= N_NODES) return;
    float s = bc[0];
    #pragma unroll
    for (int c = 0; c < 32; c++) s = fmaf(h[(size_t)i * 32 + c], __ldg(&Wc[c]), s);
    out[i] = s;
}

// ---------------- host driver ----------------
static void launch_gemm(int D, const float* A, const float* Wt, const float* b,
                        float* C, int M, int K) {
    dim3 grid((M + 63) / 64), blk(256);
    if (D == 128)      gemm_kernel<128><<<grid, blk>>>(A, Wt, b, C, M, K);
    else if (D == 64)  gemm_kernel<64><<<grid, blk>>>(A, Wt, b, C, M, K);
    else               gemm_kernel<32><<<grid, blk>>>(A, Wt, b, C, M, K);
}

static void launch_attn(int D, const float* q, const float* k, const float* v,
                        const float* e, float* h) {
    dim3 grid((N_NODES + 7) / 8), blk(256);
    if (D == 128)      attn_kernel<128><<<grid, blk>>>(q, k, v, e, h);
    else if (D == 64)  attn_kernel<64><<<grid, blk>>>(q, k, v, e, h);
    else               attn_kernel<32><<<grid, blk>>>(q, k, v, e, h);
}

extern "C" void kernel_launch(void* const* d_in, const int* in_sizes, int n_in,
                              void* d_out, int out_size) {
    const float* x  = (const float*)d_in[0];
    const void*  ei = d_in[1];
    const float* ea = (const float*)d_in[2];
    const float* W[3][9];
    int p = 3;
    for (int l = 0; l < 3; l++)
        for (int j = 0; j < 9; j++) W[l][j] = (const float*)d_in[p++];
    const float* Wc = (const float*)d_in[30];
    const float* bc = (const float*)d_in[31];

    float *qb, *kb, *vb, *hA, *hB, *eb, *eab;
    cudaGetSymbolAddress((void**)&qb,  g_q);
    cudaGetSymbolAddress((void**)&kb,  g_k);
    cudaGetSymbolAddress((void**)&vb,  g_v);
    cudaGetSymbolAddress((void**)&hA,  g_hA);
    cudaGetSymbolAddress((void**)&hB,  g_hB);
    cudaGetSymbolAddress((void**)&eb,  g_e);
    cudaGetSymbolAddress((void**)&eab, g_ea);

    // graph preprocessing (identical every launch)
    detect_kernel<<<1, 256>>>(ei);
    convert_kernel<<<(N_EDGES + 255) / 256, 256>>>(ei);
    hist_kernel<<<(N_EDGES + 255) / 256, 256>>>();
    scan_kernel<<<1, 1024>>>();
    {
        long long tot = (long long)N_EDGES * 32;
        scatter_kernel<<<(unsigned)((tot + 255) / 256), 256>>>(ea);
    }

    int din[3] = {128, 128, 64}, dout[3] = {128, 64, 32};
    const float* hin = x;
    float* houts[3] = {hA, hB, hA};
    for (int l = 0; l < 3; l++) {
        float* hout = houts[l];
        int K = din[l], D = dout[l];
        launch_gemm(D, hin, W[l][0], W[l][1], qb, N_NODES, K);   // q
        launch_gemm(D, hin, W[l][2], W[l][3], kb, N_NODES, K);   // k
        launch_gemm(D, hin, W[l][4], W[l][5], vb, N_NODES, K);   // v
        launch_gemm(D, hin, W[l][7], W[l][8], hout, N_NODES, K); // skip (Ws, bs)
        launch_gemm(D, eab, W[l][6], nullptr, eb, N_EDGES, 32);  // e = edge_attr @ We
        launch_attn(D, qb, kb, vb, eb, hout);                    // h = relu(skip + agg)
        hin = hout;
    }
    final_kernel<<<(N_NODES + 255) / 256, 256>>>(hA, Wc, bc, (float*)d_out);
}

// round 2
// speedup vs baseline: 1.3684x; 1.3684x over previous
#include <cuda_runtime.h>
#include <cstdint>

#define N_NODES 50000
#define N_EDGES 800000

// ---------------- static device scratch ----------------
__device__ float g_q[(size_t)N_NODES * 128];
__device__ float g_k[(size_t)N_NODES * 128];
__device__ float g_v[(size_t)N_NODES * 128];
__device__ float g_hA[(size_t)N_NODES * 128];
__device__ float g_hB[(size_t)N_NODES * 128];
__device__ float g_qe[(size_t)N_NODES * 32];   // qE = q @ We^T
__device__ float g_aw[(size_t)N_NODES * 32];   // sum_i a_i * ea_i
__device__ float g_ea[(size_t)N_EDGES * 32];   // edge_attr in CSR order
__device__ float g_Wqe[128 * 32];              // composite Wq @ We^T
__device__ float g_bqe[32];                    // composite bq @ We^T
__device__ int   g_src[N_EDGES];
__device__ int   g_dst[N_EDGES];
__device__ int   g_esrc[N_EDGES];
__device__ int   g_rowptr[N_NODES + 1];
__device__ int   g_cnt[N_NODES];
__device__ int   g_wofs[N_NODES];
__device__ int   g_bsum[64];
__device__ int   g_boff[64];
__device__ int   g_flag[1];

// ---------------- packed fp32x2 helpers (Blackwell dual-fp32) ----------------
__device__ __forceinline__ unsigned long long pk2(float x, float y) {
    unsigned long long r;
    asm("mov.b64 %0, {%1,%2};" : "=l"(r) : "f"(x), "f"(y));
    return r;
}
__device__ __forceinline__ void upk2(unsigned long long p, float& x, float& y) {
    asm("mov.b64 {%0,%1}, %2;" : "=f"(x), "=f"(y) : "l"(p));
}
__device__ __forceinline__ unsigned long long fma2(unsigned long long a, unsigned long long b,
                                                   unsigned long long c) {
    unsigned long long d;
    asm("fma.rn.f32x2 %0, %1, %2, %3;" : "=l"(d) : "l"(a), "l"(b), "l"(c));
    return d;
}

// ---------------- edge_index dtype detection (int32 vs int64) ----------------
__global__ void detect_kernel(const void* ei) {
    __shared__ int ok;
    if (threadIdx.x == 0) ok = 1;
    __syncthreads();
    const long long* p = (const long long*)ei;
    long long v = p[threadIdx.x];
    if (!(v >= 0 && v < (long long)N_NODES)) atomicExch(&ok, 0);
    __syncthreads();
    if (threadIdx.x == 0) g_flag[0] = ok;   // 1 => data is int64
}

__global__ void convert_kernel(const void* ei) {
    int i = blockIdx.x * blockDim.x + threadIdx.x;
    int is64 = g_flag[0];
    if (i < N_EDGES) {
        int s, d;
        if (is64) {
            const long long* p = (const long long*)ei;
            s = (int)p[i]; d = (int)p[N_EDGES + i];
        } else {
            const int* p = (const int*)ei;
            s = p[i]; d = p[N_EDGES + i];
        }
        g_src[i] = s; g_dst[i] = d;
    }
    if (i < N_NODES) g_cnt[i] = 0;
}

__global__ void hist_kernel() {
    int i = blockIdx.x * blockDim.x + threadIdx.x;
    if (i < N_EDGES) atomicAdd(&g_cnt[g_dst[i]], 1);
}

// ---------------- 3-phase parallel exclusive scan ----------------
__global__ void scanA_kernel() {
    __shared__ int wsum[32];
    int tid = threadIdx.x, lane = tid & 31, wid = tid >> 5;
    int i = blockIdx.x * 1024 + tid;
    int v = (i < N_NODES) ? g_cnt[i] : 0;
    int x = v;
    #pragma unroll
    for (int off = 1; off < 32; off <<= 1) {
        int t = __shfl_up_sync(0xffffffffu, x, off);
        if (lane >= off) x += t;
    }
    if (lane == 31) wsum[wid] = x;
    __syncthreads();
    if (wid == 0) {
        int y = wsum[lane];
        #pragma unroll
        for (int off = 1; off < 32; off <<= 1) {
            int t = __shfl_up_sync(0xffffffffu, y, off);
            if (lane >= off) y += t;
        }
        wsum[lane] = y;
    }
    __syncthreads();
    int incl = x + (wid ? wsum[wid - 1] : 0);
    if (i < N_NODES) g_rowptr[i + 1] = incl;
    if (tid == 1023) g_bsum[blockIdx.x] = incl;
}

__global__ void scanB_kernel(int nb) {
    __shared__ int w0tot;
    int tid = threadIdx.x, lane = tid & 31, wid = tid >> 5;
    int v = (tid < nb) ? g_bsum[tid] : 0;
    int x = v;
    #pragma unroll
    for (int off = 1; off < 32; off <<= 1) {
        int t = __shfl_up_sync(0xffffffffu, x, off);
        if (lane >= off) x += t;
    }
    if (wid == 0 && lane == 31) w0tot = x;
    __syncthreads();
    int incl = x + (wid ? w0tot : 0);
    g_boff[tid] = incl - v;   // exclusive block offsets
    if (tid == 0) g_rowptr[0] = 0;
}

__global__ void scanC_kernel() {
    int i = blockIdx.x * 1024 + threadIdx.x;
    if (i < N_NODES) {
        int off = g_boff[blockIdx.x];
        int r = g_rowptr[i + 1] + off;
        g_rowptr[i + 1] = r;
        g_wofs[i] = r - g_cnt[i];
    }
}

// one warp per edge: place edge into CSR slot, copy its 32 edge_attr floats
__global__ void scatter_kernel(const float* __restrict__ ea) {
    int w = (blockIdx.x * blockDim.x + threadIdx.x) >> 5;
    int lane = threadIdx.x & 31;
    if (w >= N_EDGES) return;
    int pos = 0;
    if (lane == 0) {
        int d = g_dst[w];
        pos = atomicAdd(&g_wofs[d], 1);
        g_esrc[pos] = g_src[w];
    }
    pos = __shfl_sync(0xffffffffu, pos, 0);
    g_ea[(size_t)pos * 32 + lane] = ea[(size_t)w * 32 + lane];
}

// ---------------- fused 4-output SGEMM (f32x2): Cj = A @ Wj + bj ----------------
template <int BN>
__global__ __launch_bounds__(256) void gemm4(
    const float* __restrict__ A,
    const float* __restrict__ Wa, const float* __restrict__ Wb,
    const float* __restrict__ Wc_, const float* __restrict__ Wd,
    const float* __restrict__ ba, const float* __restrict__ bb,
    const float* __restrict__ bc_, const float* __restrict__ bd,
    float* Ca, float* Cb, float* Cc, float* Cd,
    int M, int K)
{
    constexpr int BM = 128, BK = 16;
    constexpr int TN = BN / 16;     // cols per thread
    constexpr int TM = 8;           // rows per thread
    constexpr int NH = TN / 2;      // packed pairs per thread
    __shared__ float As[BK][BM + 4];
    __shared__ float Ws[BK][BN];

    const float* W; const float* bias; float* C;
    switch (blockIdx.y) {
        case 0:  W = Wa;  bias = ba;  C = Ca; break;
        case 1:  W = Wb;  bias = bb;  C = Cb; break;
        case 2:  W = Wc_; bias = bc_; C = Cc; break;
        default: W = Wd;  bias = bd;  C = Cd; break;
    }
    int tid = threadIdx.x;
    int ct = tid & 15, rt = tid >> 4;
    int row0 = blockIdx.x * BM;
    unsigned long long acc[TM][NH];
    #pragma unroll
    for (int t = 0; t < TM; t++)
        #pragma unroll
        for (int n = 0; n < NH; n++) acc[t][n] = 0ull;

    int lrow = tid >> 2;   // 0..63
    int lkq  = tid & 3;    // 0..3 (float4 within BK)

    for (int k0 = 0; k0 < K; k0 += BK) {
        #pragma unroll
        for (int it = 0; it < 2; it++) {
            int r = lrow + 64 * it;
            int gr = row0 + r;
            float4 a = make_float4(0.f, 0.f, 0.f, 0.f);
            if (gr < M) a = *(const float4*)&A[(size_t)gr * K + k0 + lkq * 4];
            As[lkq * 4 + 0][r] = a.x;
            As[lkq * 4 + 1][r] = a.y;
            As[lkq * 4 + 2][r] = a.z;
            As[lkq * 4 + 3][r] = a.w;
        }
        #pragma unroll
        for (int f = tid; f < BK * BN / 4; f += 256) {
            int kk = f / (BN / 4), n4 = f % (BN / 4);
            *(float4*)&Ws[kk][n4 * 4] = *(const float4*)&W[(size_t)(k0 + kk) * BN + n4 * 4];
        }
        __syncthreads();
        #pragma unroll
        for (int kk = 0; kk < BK; kk++) {
            float4 a0 = *(const float4*)&As[kk][rt * 8];
            float4 a1 = *(const float4*)&As[kk][rt * 8 + 4];
            float av[8] = {a0.x, a0.y, a0.z, a0.w, a1.x, a1.y, a1.z, a1.w};
            unsigned long long b2[NH];
            const unsigned long long* wp = (const unsigned long long*)&Ws[kk][ct * TN];
            #pragma unroll
            for (int n = 0; n < NH; n++) b2[n] = wp[n];
            #pragma unroll
            for (int t = 0; t < TM; t++) {
                unsigned long long a2 = pk2(av[t], av[t]);
                #pragma unroll
                for (int n = 0; n < NH; n++) acc[t][n] = fma2(a2, b2[n], acc[t][n]);
            }
        }
        __syncthreads();
    }
    float bv[TN];
    #pragma unroll
    for (int n = 0; n < TN; n++) bv[n] = bias[ct * TN + n];
    #pragma unroll
    for (int t = 0; t < TM; t++) {
        int r = row0 + rt * 8 + t;
        if (r < M) {
            #pragma unroll
            for (int n = 0; n < NH; n++) {
                float x, y; upk2(acc[t][n], x, y);
                float2 o = make_float2(x + bv[2 * n], y + bv[2 * n + 1]);
                *(float2*)&C[(size_t)r * BN + ct * TN + 2 * n] = o;
            }
        }
    }
}

// ---------------- composite weights: Wqe = Wq @ We^T, bqe = bq @ We^T ----------------
__global__ void compose_kernel(const float* __restrict__ Wq, const float* __restrict__ bq,
                               const float* __restrict__ We, int K, int D) {
    int idx = blockIdx.x * 256 + threadIdx.x;
    if (idx < K * 32) {
        int kk = idx >> 5, n = idx & 31;
        float s = 0.f;
        for (int j = 0; j < D; j++) s = fmaf(Wq[kk * D + j], We[n * D + j], s);
        g_Wqe[idx] = s;
    }
    if (idx < 32) {
        float s = 0.f;
        for (int j = 0; j < D; j++) s = fmaf(bq[j], We[idx * D + j], s);
        g_bqe[idx] = s;
    }
}

// ---------------- attention: warp per dst node, online softmax; aw is 32-dim ----------------
template <int DOUT>
__global__ void attn_kernel(const float* __restrict__ q, const float* __restrict__ k,
                            const float* __restrict__ v, const float* __restrict__ qE,
                            float* __restrict__ h, float* __restrict__ aw) {
    int w = (blockIdx.x * blockDim.x + threadIdx.x) >> 5;
    if (w >= N_NODES) return;
    int lane = threadIdx.x & 31;
    constexpr int VEC = DOUT / 32;
    float qr[VEC], acc[VEC];
    {
        const float* qp = q + (size_t)w * DOUT + lane * VEC;
        #pragma unroll
        for (int j = 0; j < VEC; j++) { qr[j] = qp[j]; acc[j] = 0.f; }
    }
    float qe_l = qE[(size_t)w * 32 + lane];
    float m = -__int_as_float(0x7f800000);
    float s = 0.f, accw = 0.f;
    int beg = g_rowptr[w], end = g_rowptr[w + 1];
    const float scale = rsqrtf((float)DOUT);
    for (int i = beg; i < end; i++) {
        int src = g_esrc[i];
        float eav = g_ea[(size_t)i * 32 + lane];
        const float* kp = k + (size_t)src * DOUT + lane * VEC;
        const float* vp = v + (size_t)src * DOUT + lane * VEC;
        float kv[VEC], vv[VEC];
        if constexpr (VEC == 4) {
            float4 kt = *(const float4*)kp; float4 vt = *(const float4*)vp;
            kv[0] = kt.x; kv[1] = kt.y; kv[2] = kt.z; kv[3] = kt.w;
            vv[0] = vt.x; vv[1] = vt.y; vv[2] = vt.z; vv[3] = vt.w;
        } else if constexpr (VEC == 2) {
            float2 kt = *(const float2*)kp; float2 vt = *(const float2*)vp;
            kv[0] = kt.x; kv[1] = kt.y;
            vv[0] = vt.x; vv[1] = vt.y;
        } else {
            kv[0] = kp[0]; vv[0] = vp[0];
        }
        float dot = qe_l * eav;
        #pragma unroll
        for (int j = 0; j < VEC; j++) dot = fmaf(qr[j], kv[j], dot);
        #pragma unroll
        for (int off = 16; off; off >>= 1) dot += __shfl_xor_sync(0xffffffffu, dot, off);
        float alpha = dot * scale;
        float nm = fmaxf(m, alpha);
        float corr = __expf(m - nm);
        float wgt = __expf(alpha - nm);
        s = s * corr + wgt;
        accw = accw * corr + wgt * eav;
        #pragma unroll
        for (int j = 0; j < VEC; j++) acc[j] = fmaf(wgt, vv[j], acc[j] * corr);
        m = nm;
    }
    float inv = (s > 0.f) ? 1.f / s : 0.f;
    float* hp = h + (size_t)w * DOUT + lane * VEC;
    #pragma unroll
    for (int j = 0; j < VEC; j++) hp[j] += acc[j] * inv;
    aw[(size_t)w * 32 + lane] = accw * inv;
}

// ---------------- agg fuse: H = relu(H + AW @ We) ----------------
template <int BN>
__global__ __launch_bounds__(256) void aggfuse(const float* __restrict__ AW,
                                               const float* __restrict__ We,
                                               float* H, int M) {
    constexpr int BM = 128, BK = 32;
    constexpr int TN = BN / 16, TM = 8, NH = TN / 2;
    __shared__ float As[BK][BM + 4];
    __shared__ float Ws[BK][BN];
    int tid = threadIdx.x;
    int ct = tid & 15, rt = tid >> 4;
    int row0 = blockIdx.x * BM;

    #pragma unroll
    for (int it = 0; it < 4; it++) {
        int f = tid + 256 * it;
        int r = f >> 3, kq = f & 7;
        int gr = row0 + r;
        float4 a = make_float4(0.f, 0.f, 0.f, 0.f);
        if (gr < M) a = *(const float4*)&AW[(size_t)gr * 32 + kq * 4];
        As[kq * 4 + 0][r] = a.x;
        As[kq * 4 + 1][r] = a.y;
        As[kq * 4 + 2][r] = a.z;
        As[kq * 4 + 3][r] = a.w;
    }
    #pragma unroll
    for (int f = tid; f < 8 * BN; f += 256) {
        int kk = f / (BN / 4), n4 = f % (BN / 4);
        *(float4*)&Ws[kk][n4 * 4] = *(const float4*)&We[(size_t)kk * BN + n4 * 4];
    }
    __syncthreads();

    unsigned long long acc[TM][NH];
    #pragma unroll
    for (int t = 0; t < TM; t++)
        #pragma unroll
        for (int n = 0; n < NH; n++) acc[t][n] = 0ull;

    #pragma unroll
    for (int kk = 0; kk < BK; kk++) {
        float4 a0 = *(const float4*)&As[kk][rt * 8];
        float4 a1 = *(const float4*)&As[kk][rt * 8 + 4];
        float av[8] = {a0.x, a0.y, a0.z, a0.w, a1.x, a1.y, a1.z, a1.w};
        unsigned long long b2[NH];
        const unsigned long long* wp = (const unsigned long long*)&Ws[kk][ct * TN];
        #pragma unroll
        for (int n = 0; n < NH; n++) b2[n] = wp[n];
        #pragma unroll
        for (int t = 0; t < TM; t++) {
            unsigned long long a2 = pk2(av[t], av[t]);
            #pragma unroll
            for (int n = 0; n < NH; n++) acc[t][n] = fma2(a2, b2[n], acc[t][n]);
        }
    }
    #pragma unroll
    for (int t = 0; t < TM; t++) {
        int r = row0 + rt * 8 + t;
        if (r < M) {
            #pragma unroll
            for (int n = 0; n < NH; n++) {
                float x, y; upk2(acc[t][n], x, y);
                float2 hprev = *(const float2*)&H[(size_t)r * BN + ct * TN + 2 * n];
                float2 o = make_float2(fmaxf(hprev.x + x, 0.f), fmaxf(hprev.y + y, 0.f));
                *(float2*)&H[(size_t)r * BN + ct * TN + 2 * n] = o;
            }
        }
    }
}

// ---------------- final linear ----------------
__global__ void final_kernel(const float* __restrict__ h, const float* __restrict__ Wc,
                             const float* __restrict__ bc, float* __restrict__ out) {
    int i = blockIdx.x * blockDim.x + threadIdx.x;
    if (i >= N_NODES) return;
    float s = bc[0];
    #pragma unroll
    for (int c = 0; c < 32; c++) s = fmaf(h[(size_t)i * 32 + c], __ldg(&Wc[c]), s);
    out[i] = s;
}

// ---------------- host driver ----------------
extern "C" void kernel_launch(void* const* d_in, const int* in_sizes, int n_in,
                              void* d_out, int out_size) {
    const float* x  = (const float*)d_in[0];
    const void*  ei = d_in[1];
    const float* ea = (const float*)d_in[2];
    const float* W[3][9];
    int p = 3;
    for (int l = 0; l < 3; l++)
        for (int j = 0; j < 9; j++) W[l][j] = (const float*)d_in[p++];
    const float* Wc = (const float*)d_in[30];
    const float* bc = (const float*)d_in[31];

    float *qb, *kb, *vb, *hA, *hB, *qeb, *awb, *Wqeb, *bqeb;
    cudaGetSymbolAddress((void**)&qb,   g_q);
    cudaGetSymbolAddress((void**)&kb,   g_k);
    cudaGetSymbolAddress((void**)&vb,   g_v);
    cudaGetSymbolAddress((void**)&hA,   g_hA);
    cudaGetSymbolAddress((void**)&hB,   g_hB);
    cudaGetSymbolAddress((void**)&qeb,  g_qe);
    cudaGetSymbolAddress((void**)&awb,  g_aw);
    cudaGetSymbolAddress((void**)&Wqeb, g_Wqe);
    cudaGetSymbolAddress((void**)&bqeb, g_bqe);

    // graph preprocessing
    detect_kernel<<<1, 256>>>(ei);
    convert_kernel<<<(N_EDGES + 255) / 256, 256>>>(ei);
    hist_kernel<<<(N_EDGES + 255) / 256, 256>>>();
    int NB = (N_NODES + 1023) / 1024;
    scanA_kernel<<<NB, 1024>>>();
    scanB_kernel<<<1, 64>>>(NB);
    scanC_kernel<<<NB, 1024>>>();
    {
        long long tot = (long long)N_EDGES * 32;
        scatter_kernel<<<(unsigned)((tot + 255) / 256), 256>>>(ea);
    }

    int din[3] = {128, 128, 64}, dout[3] = {128, 64, 32};
    const float* hin = x;
    float* houts[3] = {hA, hB, hA};
    int gx = (N_NODES + 127) / 128;
    for (int l = 0; l < 3; l++) {
        float* hout = houts[l];
        int K = din[l], D = dout[l];
        // fused QKVS GEMM
        dim3 grid4(gx, 4);
        if (D == 128)
            gemm4<128><<<grid4, 256>>>(hin, W[l][0], W[l][2], W[l][4], W[l][7],
                                       W[l][1], W[l][3], W[l][5], W[l][8],
                                       qb, kb, vb, hout, N_NODES, K);
        else if (D == 64)
            gemm4<64><<<grid4, 256>>>(hin, W[l][0], W[l][2], W[l][4], W[l][7],
                                      W[l][1], W[l][3], W[l][5], W[l][8],
                                      qb, kb, vb, hout, N_NODES, K);
        else
            gemm4<32><<<grid4, 256>>>(hin, W[l][0], W[l][2], W[l][4], W[l][7],
                                      W[l][1], W[l][3], W[l][5], W[l][8],
                                      qb, kb, vb, hout, N_NODES, K);
        // composite edge-query weights, then qE = hin @ Wqe + bqe
        compose_kernel<<<(K * 32 + 255) / 256, 256>>>(W[l][0], W[l][1], W[l][6], K, D);
        gemm4<32><<<dim3(gx, 1), 256>>>(hin, Wqeb, nullptr, nullptr, nullptr,
                                        bqeb, nullptr, nullptr, nullptr,
                                        qeb, nullptr, nullptr, nullptr, N_NODES, K);
        // attention
        dim3 agrid((N_NODES * 32 + 255) / 256);
        if (D == 128)      attn_kernel<128><<<agrid, 256>>>(qb, kb, vb, qeb, hout, awb);
        else if (D == 64)  attn_kernel<64><<<agrid, 256>>>(qb, kb, vb, qeb, hout, awb);
        else               attn_kernel<32><<<agrid, 256>>>(qb, kb, vb, qeb, hout, awb);
        // H = relu(H + AW @ We)
        if (D == 128)      aggfuse<128><<<gx, 256>>>(awb, W[l][6], hout, N_NODES);
        else if (D == 64)  aggfuse<64><<<gx, 256>>>(awb, W[l][6], hout, N_NODES);
        else               aggfuse<32><<<gx, 256>>>(awb, W[l][6], hout, N_NODES);
        hin = hout;
    }
    final_kernel<<<(N_NODES + 255) / 256, 256>>>(hA, Wc, bc, (float*)d_out);
}

// round 4
// speedup vs baseline: 1.4530x; 1.0618x over previous
#include <cuda_runtime.h>
#include <cuda_pipeline.h>
#include <cstdint>

#define N_NODES 50000
#define N_EDGES 800000

// ---------------- static device scratch ----------------
__device__ float g_q[(size_t)N_NODES * 128];
__device__ float g_k[(size_t)N_NODES * 128];
__device__ float g_v[(size_t)N_NODES * 128];
__device__ float g_hA[(size_t)N_NODES * 128];
__device__ float g_hB[(size_t)N_NODES * 128];
__device__ float g_qe[(size_t)N_NODES * 32];   // qE = q @ We^T
__device__ float g_aw[(size_t)N_NODES * 32];   // sum_i a_i * ea_i
__device__ float g_ea[(size_t)N_EDGES * 32];   // edge_attr in CSR order
__device__ float g_Wqe[128 * 32];              // composite Wq @ We^T
__device__ float g_bqe[32];                    // composite bq @ We^T
__device__ int   g_src[N_EDGES];
__device__ int   g_dst[N_EDGES];
__device__ int   g_esrc[N_EDGES];
__device__ int   g_rowptr[N_NODES + 1];
__device__ int   g_cnt[N_NODES];
__device__ int   g_wofs[N_NODES];
__device__ int   g_bsum[64];
__device__ int   g_boff[64];
__device__ int   g_flag[1];

// ---------------- packed fp32x2 helpers ----------------
__device__ __forceinline__ unsigned long long pk2(float x, float y) {
    unsigned long long r;
    asm("mov.b64 %0, {%1,%2};" : "=l"(r) : "f"(x), "f"(y));
    return r;
}
__device__ __forceinline__ void upk2(unsigned long long p, float& x, float& y) {
    asm("mov.b64 {%0,%1}, %2;" : "=f"(x), "=f"(y) : "l"(p));
}
__device__ __forceinline__ unsigned long long fma2(unsigned long long a, unsigned long long b,
                                                   unsigned long long c) {
    unsigned long long d;
    asm("fma.rn.f32x2 %0, %1, %2, %3;" : "=l"(d) : "l"(a), "l"(b), "l"(c));
    return d;
}

// ---------------- edge_index dtype detection ----------------
__global__ void detect_kernel(const void* ei) {
    __shared__ int ok;
    if (threadIdx.x == 0) ok = 1;
    __syncthreads();
    const long long* p = (const long long*)ei;
    long long v = p[threadIdx.x];
    if (!(v >= 0 && v < (long long)N_NODES)) atomicExch(&ok, 0);
    __syncthreads();
    if (threadIdx.x == 0) g_flag[0] = ok;
}

__global__ void convert_kernel(const void* ei) {
    int i = blockIdx.x * blockDim.x + threadIdx.x;
    int is64 = g_flag[0];
    if (i < N_EDGES) {
        int s, d;
        if (is64) {
            const long long* p = (const long long*)ei;
            s = (int)p[i]; d = (int)p[N_EDGES + i];
        } else {
            const int* p = (const int*)ei;
            s = p[i]; d = p[N_EDGES + i];
        }
        g_src[i] = s; g_dst[i] = d;
    }
    if (i < N_NODES) g_cnt[i] = 0;
}

__global__ void hist_kernel() {
    int i = blockIdx.x * blockDim.x + threadIdx.x;
    if (i < N_EDGES) atomicAdd(&g_cnt[g_dst[i]], 1);
}

// ---------------- 3-phase parallel exclusive scan ----------------
__global__ void scanA_kernel() {
    __shared__ int wsum[32];
    int tid = threadIdx.x, lane = tid & 31, wid = tid >> 5;
    int i = blockIdx.x * 1024 + tid;
    int v = (i < N_NODES) ? g_cnt[i] : 0;
    int x = v;
    #pragma unroll
    for (int off = 1; off < 32; off <<= 1) {
        int t = __shfl_up_sync(0xffffffffu, x, off);
        if (lane >= off) x += t;
    }
    if (lane == 31) wsum[wid] = x;
    __syncthreads();
    if (wid == 0) {
        int y = wsum[lane];
        #pragma unroll
        for (int off = 1; off < 32; off <<= 1) {
            int t = __shfl_up_sync(0xffffffffu, y, off);
            if (lane >= off) y += t;
        }
        wsum[lane] = y;
    }
    __syncthreads();
    int incl = x + (wid ? wsum[wid - 1] : 0);
    if (i < N_NODES) g_rowptr[i + 1] = incl;
    if (tid == 1023) g_bsum[blockIdx.x] = incl;
}

__global__ void scanB_kernel(int nb) {
    __shared__ int w0tot;
    int tid = threadIdx.x, lane = tid & 31, wid = tid >> 5;
    int v = (tid < nb) ? g_bsum[tid] : 0;
    int x = v;
    #pragma unroll
    for (int off = 1; off < 32; off <<= 1) {
        int t = __shfl_up_sync(0xffffffffu, x, off);
        if (lane >= off) x += t;
    }
    if (wid == 0 && lane == 31) w0tot = x;
    __syncthreads();
    int incl = x + (wid ? w0tot : 0);
    g_boff[tid] = incl - v;
    if (tid == 0) g_rowptr[0] = 0;
}

__global__ void scanC_kernel() {
    int i = blockIdx.x * 1024 + threadIdx.x;
    if (i < N_NODES) {
        int off = g_boff[blockIdx.x];
        int r = g_rowptr[i + 1] + off;
        g_rowptr[i + 1] = r;
        g_wofs[i] = r - g_cnt[i];
    }
}

__global__ void scatter_kernel(const float* __restrict__ ea) {
    int w = (blockIdx.x * blockDim.x + threadIdx.x) >> 5;
    int lane = threadIdx.x & 31;
    if (w >= N_EDGES) return;
    int pos = 0;
    if (lane == 0) {
        int d = g_dst[w];
        pos = atomicAdd(&g_wofs[d], 1);
        g_esrc[pos] = g_src[w];
    }
    pos = __shfl_sync(0xffffffffu, pos, 0);
    g_ea[(size_t)pos * 32 + lane] = ea[(size_t)w * 32 + lane];
}

// ---------------- fused 4-output SGEMM, double-buffered, cp.async W ----------------
template <int BN>
__global__ __launch_bounds__(256, 2) void gemm4(
    const float* __restrict__ A,
    const float* __restrict__ Wa, const float* __restrict__ Wb,
    const float* __restrict__ Wc_, const float* __restrict__ Wd,
    const float* __restrict__ ba, const float* __restrict__ bb,
    const float* __restrict__ bc_, const float* __restrict__ bd,
    float* Ca, float* Cb, float* Cc, float* Cd,
    int M, int K)
{
    constexpr int BM = 128, BK = 16;
    constexpr int TN = BN / 16;     // cols per thread
    constexpr int TM = 8;           // rows per thread
    constexpr int NH = TN / 2;      // packed pairs per thread
    __shared__ float As[2][BK][BM + 4];
    __shared__ float Ws[2][BK][BN];

    const float* W; const float* bias; float* C;
    switch (blockIdx.y) {
        case 0:  W = Wa;  bias = ba;  C = Ca; break;
        case 1:  W = Wb;  bias = bb;  C = Cb; break;
        case 2:  W = Wc_; bias = bc_; C = Cc; break;
        default: W = Wd;  bias = bd;  C = Cd; break;
    }
    int tid = threadIdx.x;
    int ct = tid & 15, rt = tid >> 4;
    int row0 = blockIdx.x * BM;
    const int NS = K / BK;

    unsigned long long acc[TM][NH];
    #pragma unroll
    for (int t = 0; t < TM; t++)
        #pragma unroll
        for (int n = 0; n < NH; n++) acc[t][n] = 0ull;

    int lr = tid >> 2;   // row for A loads (two chunks: lr, lr+64... actually f>>2)
    int lkq = tid & 3;   // float4 index within BK

    float4 areg[2];
    // ---- prologue: stage 0 ----
    #pragma unroll
    for (int it = 0; it < 2; it++) {
        int r = lr + 64 * it;
        int gr = row0 + r;
        areg[it] = make_float4(0.f, 0.f, 0.f, 0.f);
        if (gr < M) areg[it] = *(const float4*)&A[(size_t)gr * K + lkq * 4];
    }
    #pragma unroll
    for (int f = tid; f < 4 * BN; f += 256) {
        int kk = f / (BN / 4), n4 = f % (BN / 4);
        __pipeline_memcpy_async(&Ws[0][kk][n4 * 4], &W[(size_t)kk * BN + n4 * 4], 16);
    }
    __pipeline_commit();
    #pragma unroll
    for (int it = 0; it < 2; it++) {
        int r = lr + 64 * it;
        As[0][lkq * 4 + 0][r] = areg[it].x;
        As[0][lkq * 4 + 1][r] = areg[it].y;
        As[0][lkq * 4 + 2][r] = areg[it].z;
        As[0][lkq * 4 + 3][r] = areg[it].w;
    }
    __pipeline_wait_prior(0);
    __syncthreads();

    for (int s = 0; s < NS; s++) {
        int cur = s & 1, nxt = cur ^ 1;
        bool more = (s + 1 < NS);
        if (more) {
            int k0n = (s + 1) * BK;
            #pragma unroll
            for (int it = 0; it < 2; it++) {
                int r = lr + 64 * it;
                int gr = row0 + r;
                areg[it] = make_float4(0.f, 0.f, 0.f, 0.f);
                if (gr < M) areg[it] = *(const float4*)&A[(size_t)gr * K + k0n + lkq * 4];
            }
            #pragma unroll
            for (int f = tid; f < 4 * BN; f += 256) {
                int kk = f / (BN / 4), n4 = f % (BN / 4);
                __pipeline_memcpy_async(&Ws[nxt][kk][n4 * 4],
                                        &W[(size_t)(k0n + kk) * BN + n4 * 4], 16);
            }
            __pipeline_commit();
        }
        #pragma unroll
        for (int kk = 0; kk < BK; kk++) {
            float4 a0 = *(const float4*)&As[cur][kk][rt * 8];
            float4 a1 = *(const float4*)&As[cur][kk][rt * 8 + 4];
            float av[8] = {a0.x, a0.y, a0.z, a0.w, a1.x, a1.y, a1.z, a1.w};
            unsigned long long b2[NH];
            const float* wp = &Ws[cur][kk][ct * TN];
            if constexpr (NH == 4) {
                ulonglong2 p0 = ((const ulonglong2*)wp)[0];
                ulonglong2 p1 = ((const ulonglong2*)wp)[1];
                b2[0] = p0.x; b2[1] = p0.y; b2[2] = p1.x; b2[3] = p1.y;
            } else if constexpr (NH == 2) {
                ulonglong2 p0 = ((const ulonglong2*)wp)[0];
                b2[0] = p0.x; b2[1] = p0.y;
            } else {
                b2[0] = *(const unsigned long long*)wp;
            }
            #pragma unroll
            for (int t = 0; t < TM; t++) {
                unsigned long long a2 = pk2(av[t], av[t]);
                #pragma unroll
                for (int n = 0; n < NH; n++) acc[t][n] = fma2(a2, b2[n], acc[t][n]);
            }
        }
        if (more) {
            #pragma unroll
            for (int it = 0; it < 2; it++) {
                int r = lr + 64 * it;
                As[nxt][lkq * 4 + 0][r] = areg[it].x;
                As[nxt][lkq * 4 + 1][r] = areg[it].y;
                As[nxt][lkq * 4 + 2][r] = areg[it].z;
                As[nxt][lkq * 4 + 3][r] = areg[it].w;
            }
            __pipeline_wait_prior(0);
            __syncthreads();
        }
    }

    float bv[TN];
    #pragma unroll
    for (int n = 0; n < TN; n++) bv[n] = bias[ct * TN + n];
    #pragma unroll
    for (int t = 0; t < TM; t++) {
        int r = row0 + rt * 8 + t;
        if (r < M) {
            #pragma unroll
            for (int n = 0; n < NH; n++) {
                float x, y; upk2(acc[t][n], x, y);
                float2 o = make_float2(x + bv[2 * n], y + bv[2 * n + 1]);
                *(float2*)&C[(size_t)r * BN + ct * TN + 2 * n] = o;
            }
        }
    }
}

// ---------------- composite weights: Wqe = Wq @ We^T ----------------
__global__ void compose_kernel(const float* __restrict__ Wq, const float* __restrict__ bq,
                               const float* __restrict__ We, int K, int D) {
    int idx = blockIdx.x * 256 + threadIdx.x;
    if (idx < K * 32) {
        int kk = idx >> 5, n = idx & 31;
        float s = 0.f;
        for (int j = 0; j < D; j++) s = fmaf(Wq[kk * D + j], We[n * D + j], s);
        g_Wqe[idx] = s;
    }
    if (idx < 32) {
        float s = 0.f;
        for (int j = 0; j < D; j++) s = fmaf(bq[j], We[idx * D + j], s);
        g_bqe[idx] = s;
    }
}

// ---------------- attention: warp per dst node, online softmax, 1-deep prefetch ----------------
template <int DOUT>
__global__ void attn_kernel(const float* __restrict__ q, const float* __restrict__ k,
                            const float* __restrict__ v, const float* __restrict__ qE,
                            float* __restrict__ h, float* __restrict__ aw) {
    int w = (blockIdx.x * blockDim.x + threadIdx.x) >> 5;
    if (w >= N_NODES) return;
    int lane = threadIdx.x & 31;
    constexpr int VEC = DOUT / 32;
    float qr[VEC], acc[VEC];
    {
        const float* qp = q + (size_t)w * DOUT + lane * VEC;
        #pragma unroll
        for (int j = 0; j < VEC; j++) { qr[j] = qp[j]; acc[j] = 0.f; }
    }
    float qe_l = qE[(size_t)w * 32 + lane];
    float m = -__int_as_float(0x7f800000);
    float s = 0.f, accw = 0.f;
    int beg = g_rowptr[w], end = g_rowptr[w + 1];
    const float scale = rsqrtf((float)DOUT);

    float kc[VEC], vc[VEC], eac = 0.f;
    if (beg < end) {
        int src = g_esrc[beg];
        eac = g_ea[(size_t)beg * 32 + lane];
        const float* kp = k + (size_t)src * DOUT + lane * VEC;
        const float* vp = v + (size_t)src * DOUT + lane * VEC;
        if constexpr (VEC == 4) {
            float4 kt = *(const float4*)kp; float4 vt = *(const float4*)vp;
            kc[0] = kt.x; kc[1] = kt.y; kc[2] = kt.z; kc[3] = kt.w;
            vc[0] = vt.x; vc[1] = vt.y; vc[2] = vt.z; vc[3] = vt.w;
        } else if constexpr (VEC == 2) {
            float2 kt = *(const float2*)kp; float2 vt = *(const float2*)vp;
            kc[0] = kt.x; kc[1] = kt.y; vc[0] = vt.x; vc[1] = vt.y;
        } else { kc[0] = kp[0]; vc[0] = vp[0]; }
    }

    for (int i = beg; i < end; i++) {
        float eav = eac;
        float kv[VEC], vv[VEC];
        #pragma unroll
        for (int j = 0; j < VEC; j++) { kv[j] = kc[j]; vv[j] = vc[j]; }
        if (i + 1 < end) {   // prefetch next edge
            int src = g_esrc[i + 1];
            eac = g_ea[(size_t)(i + 1) * 32 + lane];
            const float* kp = k + (size_t)src * DOUT + lane * VEC;
            const float* vp = v + (size_t)src * DOUT + lane * VEC;
            if constexpr (VEC == 4) {
                float4 kt = *(const float4*)kp; float4 vt = *(const float4*)vp;
                kc[0] = kt.x; kc[1] = kt.y; kc[2] = kt.z; kc[3] = kt.w;
                vc[0] = vt.x; vc[1] = vt.y; vc[2] = vt.z; vc[3] = vt.w;
            } else if constexpr (VEC == 2) {
                float2 kt = *(const float2*)kp; float2 vt = *(const float2*)vp;
                kc[0] = kt.x; kc[1] = kt.y; vc[0] = vt.x; vc[1] = vt.y;
            } else { kc[0] = kp[0]; vc[0] = vp[0]; }
        }
        float dot = qe_l * eav;
        #pragma unroll
        for (int j = 0; j < VEC; j++) dot = fmaf(qr[j], kv[j], dot);
        #pragma unroll
        for (int off = 16; off; off >>= 1) dot += __shfl_xor_sync(0xffffffffu, dot, off);
        float alpha = dot * scale;
        float nm = fmaxf(m, alpha);
        float corr = __expf(m - nm);
        float wgt = __expf(alpha - nm);
        s = s * corr + wgt;
        accw = accw * corr + wgt * eav;
        #pragma unroll
        for (int j = 0; j < VEC; j++) acc[j] = fmaf(wgt, vv[j], acc[j] * corr);
        m = nm;
    }
    float inv = (s > 0.f) ? 1.f / s : 0.f;
    float* hp = h + (size_t)w * DOUT + lane * VEC;
    #pragma unroll
    for (int j = 0; j < VEC; j++) hp[j] += acc[j] * inv;
    aw[(size_t)w * 32 + lane] = accw * inv;
}

// ---------------- agg fuse: H = relu(H + AW @ We) ----------------
template <int BN>
__global__ __launch_bounds__(256) void aggfuse(const float* __restrict__ AW,
                                               const float* __restrict__ We,
                                               float* H, int M) {
    constexpr int BM = 128, BK = 32;
    constexpr int TN = BN / 16, TM = 8, NH = TN / 2;
    __shared__ float As[BK][BM + 4];
    __shared__ float Ws[BK][BN];
    int tid = threadIdx.x;
    int ct = tid & 15, rt = tid >> 4;
    int row0 = blockIdx.x * BM;

    #pragma unroll
    for (int it = 0; it < 4; it++) {
        int f = tid + 256 * it;
        int r = f >> 3, kq = f & 7;
        int gr = row0 + r;
        float4 a = make_float4(0.f, 0.f, 0.f, 0.f);
        if (gr < M) a = *(const float4*)&AW[(size_t)gr * 32 + kq * 4];
        As[kq * 4 + 0][r] = a.x;
        As[kq * 4 + 1][r] = a.y;
        As[kq * 4 + 2][r] = a.z;
        As[kq * 4 + 3][r] = a.w;
    }
    #pragma unroll
    for (int f = tid; f < 8 * BN; f += 256) {
        int kk = f / (BN / 4), n4 = f % (BN / 4);
        *(float4*)&Ws[kk][n4 * 4] = *(const float4*)&We[(size_t)kk * BN + n4 * 4];
    }
    __syncthreads();

    unsigned long long acc[TM][NH];
    #pragma unroll
    for (int t = 0; t < TM; t++)
        #pragma unroll
        for (int n = 0; n < NH; n++) acc[t][n] = 0ull;

    #pragma unroll
    for (int kk = 0; kk < BK; kk++) {
        float4 a0 = *(const float4*)&As[kk][rt * 8];
        float4 a1 = *(const float4*)&As[kk][rt * 8 + 4];
        float av[8] = {a0.x, a0.y, a0.z, a0.w, a1.x, a1.y, a1.z, a1.w};
        unsigned long long b2[NH];
        const float* wp = &Ws[kk][ct * TN];
        if constexpr (NH == 4) {
            ulonglong2 p0 = ((const ulonglong2*)wp)[0];
            ulonglong2 p1 = ((const ulonglong2*)wp)[1];
            b2[0] = p0.x; b2[1] = p0.y; b2[2] = p1.x; b2[3] = p1.y;
        } else if constexpr (NH == 2) {
            ulonglong2 p0 = ((const ulonglong2*)wp)[0];
            b2[0] = p0.x; b2[1] = p0.y;
        } else {
            b2[0] = *(const unsigned long long*)wp;
        }
        #pragma unroll
        for (int t = 0; t < TM; t++) {
            unsigned long long a2 = pk2(av[t], av[t]);
            #pragma unroll
            for (int n = 0; n < NH; n++) acc[t][n] = fma2(a2, b2[n], acc[t][n]);
        }
    }
    #pragma unroll
    for (int t = 0; t < TM; t++) {
        int r = row0 + rt * 8 + t;
        if (r < M) {
            #pragma unroll
            for (int n = 0; n < NH; n++) {
                float x, y; upk2(acc[t][n], x, y);
                float2 hprev = *(const float2*)&H[(size_t)r * BN + ct * TN + 2 * n];
                float2 o = make_float2(fmaxf(hprev.x + x, 0.f), fmaxf(hprev.y + y, 0.f));
                *(float2*)&H[(size_t)r * BN + ct * TN + 2 * n] = o;
            }
        }
    }
}

// ---------------- final linear ----------------
__global__ void final_kernel(const float* __restrict__ h, const float* __restrict__ Wc,
                             const float* __restrict__ bc, float* __restrict__ out) {
    int i = blockIdx.x * blockDim.x + threadIdx.x;
    if (i >= N_NODES) return;
    float s = bc[0];
    #pragma unroll
    for (int c = 0; c < 32; c++) s = fmaf(h[(size_t)i * 32 + c], __ldg(&Wc[c]), s);
    out[i] = s;
}

// ---------------- host driver ----------------
extern "C" void kernel_launch(void* const* d_in, const int* in_sizes, int n_in,
                              void* d_out, int out_size) {
    const float* x  = (const float*)d_in[0];
    const void*  ei = d_in[1];
    const float* ea = (const float*)d_in[2];
    const float* W[3][9];
    int p = 3;
    for (int l = 0; l < 3; l++)
        for (int j = 0; j < 9; j++) W[l][j] = (const float*)d_in[p++];
    const float* Wc = (const float*)d_in[30];
    const float* bc = (const float*)d_in[31];

    float *qb, *kb, *vb, *hA, *hB, *qeb, *awb, *Wqeb, *bqeb;
    cudaGetSymbolAddress((void**)&qb,   g_q);
    cudaGetSymbolAddress((void**)&kb,   g_k);
    cudaGetSymbolAddress((void**)&vb,   g_v);
    cudaGetSymbolAddress((void**)&hA,   g_hA);
    cudaGetSymbolAddress((void**)&hB,   g_hB);
    cudaGetSymbolAddress((void**)&qeb,  g_qe);
    cudaGetSymbolAddress((void**)&awb,  g_aw);
    cudaGetSymbolAddress((void**)&Wqeb, g_Wqe);
    cudaGetSymbolAddress((void**)&bqeb, g_bqe);

    // graph preprocessing
    detect_kernel<<<1, 256>>>(ei);
    convert_kernel<<<(N_EDGES + 255) / 256, 256>>>(ei);
    hist_kernel<<<(N_EDGES + 255) / 256, 256>>>();
    int NB = (N_NODES + 1023) / 1024;
    scanA_kernel<<<NB, 1024>>>();
    scanB_kernel<<<1, 64>>>(NB);
    scanC_kernel<<<NB, 1024>>>();
    {
        long long tot = (long long)N_EDGES * 32;
        scatter_kernel<<<(unsigned)((tot + 255) / 256), 256>>>(ea);
    }

    int din[3] = {128, 128, 64}, dout[3] = {128, 64, 32};
    const float* hin = x;
    float* houts[3] = {hA, hB, hA};
    int gx = (N_NODES + 127) / 128;
    for (int l = 0; l < 3; l++) {
        float* hout = houts[l];
        int K = din[l], D = dout[l];
        dim3 grid4(gx, 4);
        if (D == 128)
            gemm4<128><<<grid4, 256>>>(hin, W[l][0], W[l][2], W[l][4], W[l][7],
                                       W[l][1], W[l][3], W[l][5], W[l][8],
                                       qb, kb, vb, hout, N_NODES, K);
        else if (D == 64)
            gemm4<64><<<grid4, 256>>>(hin, W[l][0], W[l][2], W[l][4], W[l][7],
                                      W[l][1], W[l][3], W[l][5], W[l][8],
                                      qb, kb, vb, hout, N_NODES, K);
        else
            gemm4<32><<<grid4, 256>>>(hin, W[l][0], W[l][2], W[l][4], W[l][7],
                                      W[l][1], W[l][3], W[l][5], W[l][8],
                                      qb, kb, vb, hout, N_NODES, K);
        compose_kernel<<<(K * 32 + 255) / 256, 256>>>(W[l][0], W[l][1], W[l][6], K, D);
        gemm4<32><<<dim3(gx, 1), 256>>>(hin, Wqeb, nullptr, nullptr, nullptr,
                                        bqeb, nullptr, nullptr, nullptr,
                                        qeb, nullptr, nullptr, nullptr, N_NODES, K);
        dim3 agrid((N_NODES * 32 + 255) / 256);
        if (D == 128)      attn_kernel<128><<<agrid, 256>>>(qb, kb, vb, qeb, hout, awb);
        else if (D == 64)  attn_kernel<64><<<agrid, 256>>>(qb, kb, vb, qeb, hout, awb);
        else               attn_kernel<32><<<agrid, 256>>>(qb, kb, vb, qeb, hout, awb);
        if (D == 128)      aggfuse<128><<<gx, 256>>>(awb, W[l][6], hout, N_NODES);
        else if (D == 64)  aggfuse<64><<<gx, 256>>>(awb, W[l][6], hout, N_NODES);
        else               aggfuse<32><<<gx, 256>>>(awb, W[l][6], hout, N_NODES);
        hin = hout;
    }
    final_kernel<<<(N_NODES + 255) / 256, 256>>>(hA, Wc, bc, (float*)d_out);
}